// round 16
// baseline (speedup 1.0000x reference)
#include <cuda_runtime.h>
#include <math.h>

#define TOKENS   16384
#define NEXP     256
#define HID      7168
#define NGROUP   8
#define TOPKG    4
#define TOPKN    8

#define KC      248          // Eigen kc panel
#define NPANEL  29           // 28 full panels (248) + remainder (224)

// Per-panel partial sums: part[p][t*E+e]. 29 * 16M floats = 487 MB.
__device__ float g_part[NPANEL][TOKENS * NEXP];

// ---------------------------------------------------------------------------
// Kernel 1: panel GEMM. FROZEN NUMERICS: each output of panel p is ONE serial
// ascending-k fma chain over its kc slice (fma.rn.f32x2 lanes = independent
// rn-FMAs). Panels folded in ascending order by router_topk (Eigen order).
// R16 change: b-stable FFMA2 schedule (bq[jp] fixed in slot b across 4
// consecutive FFMA2s; i split into 2 halves of 4 to cap live regs) —
// targets operand-reuse on slot b => rt 3 -> 2.
// ---------------------------------------------------------------------------
#define BM 128
#define BN 128
#define BK 16
#define TPAD 4
#define TROW (BM + TPAD)     // 132
#define TILE_F (BK * TROW)   // 2112 floats

#define FMA2(acc, a, b) \
    asm("fma.rn.f32x2 %0, %1, %2, %0;" : "+l"(acc) : "l"(a), "l"(b))
#define SPLAT2(p, f) \
    asm("mov.b64 %0, {%1, %1};" : "=l"(p) : "f"(f))

__global__ __launch_bounds__(256, 2) void router_gemm_panel(
    const float* __restrict__ A,   // [T, H]
    const float* __restrict__ B,   // [E, H]
    int T, int H, int E)
{
    __shared__ float sAs[2][TILE_F];
    __shared__ float sBs[2][TILE_F];

    const int tid = threadIdx.x;
    const int tx = tid & 15;
    const int ty = tid >> 4;
    const int tile_m = blockIdx.y * BM;
    const int tile_n = blockIdx.x * BN;
    const int p = blockIdx.z;
    const int kbase = p * KC;
    const bool last_panel = (p == NPANEL - 1);
    const int nfull = last_panel ? 14 : 15;   // full BK=16 iterations
    const bool has_tail = !last_panel;        // 8-k tail for 248-panels

    const int lrow = tid >> 1;
    const int lcol = (tid & 1) * 8;

    const float* Ab = A + (size_t)(tile_m + lrow) * H + kbase + lcol;
    const float* Bb = B + (size_t)(tile_n + lrow) * H + kbase + lcol;

    // acc[i][jp] = packed pair (col 2jp, 2jp+1) of row i
    unsigned long long acc[8][4];
    #pragma unroll
    for (int i = 0; i < 8; i++)
        #pragma unroll
        for (int jp = 0; jp < 4; jp++) acc[i][jp] = 0ull;

    // preload tile 0 (16 cols)
    {
        float4 a0 = *reinterpret_cast<const float4*>(Ab + 0);
        float4 a1 = *reinterpret_cast<const float4*>(Ab + 4);
        float4 b0 = *reinterpret_cast<const float4*>(Bb + 0);
        float4 b1 = *reinterpret_cast<const float4*>(Bb + 4);
        float* dA = sAs[0];
        float* dB = sBs[0];
        dA[(lcol + 0) * TROW + lrow] = a0.x; dA[(lcol + 1) * TROW + lrow] = a0.y;
        dA[(lcol + 2) * TROW + lrow] = a0.z; dA[(lcol + 3) * TROW + lrow] = a0.w;
        dA[(lcol + 4) * TROW + lrow] = a1.x; dA[(lcol + 5) * TROW + lrow] = a1.y;
        dA[(lcol + 6) * TROW + lrow] = a1.z; dA[(lcol + 7) * TROW + lrow] = a1.w;
        dB[(lcol + 0) * TROW + lrow] = b0.x; dB[(lcol + 1) * TROW + lrow] = b0.y;
        dB[(lcol + 2) * TROW + lrow] = b0.z; dB[(lcol + 3) * TROW + lrow] = b0.w;
        dB[(lcol + 4) * TROW + lrow] = b1.x; dB[(lcol + 5) * TROW + lrow] = b1.y;
        dB[(lcol + 6) * TROW + lrow] = b1.z; dB[(lcol + 7) * TROW + lrow] = b1.w;
    }
    __syncthreads();

    const int niters = nfull + (has_tail ? 1 : 0);

    for (int it = 0; it < nfull; it++) {
        const int buf = it & 1;
        const bool has_next = (it + 1) < niters;

        float4 pa0, pa1, pb0, pb1;
        if (has_next) {
            const float* an = Ab + (size_t)(it + 1) * BK;
            const float* bn = Bb + (size_t)(it + 1) * BK;
            pa0 = *reinterpret_cast<const float4*>(an + 0);
            pa1 = *reinterpret_cast<const float4*>(an + 4);
            pb0 = *reinterpret_cast<const float4*>(bn + 0);
            pb1 = *reinterpret_cast<const float4*>(bn + 4);
        }

        const float* As = sAs[buf];
        const float* Bs = sBs[buf];

        #pragma unroll
        for (int k = 0; k < BK; k++) {
            ulonglong2 bp0 = *reinterpret_cast<const ulonglong2*>(Bs + k * TROW + tx * 8);
            ulonglong2 bp1 = *reinterpret_cast<const ulonglong2*>(Bs + k * TROW + tx * 8 + 4);
            unsigned long long bq[4] = {bp0.x, bp0.y, bp1.x, bp1.y};
            float4 a0 = *reinterpret_cast<const float4*>(As + k * TROW + ty * 8);
            float4 a1 = *reinterpret_cast<const float4*>(As + k * TROW + ty * 8 + 4);
            // half 1: rows 0..3 — bq[jp] stable across 4 consecutive FFMA2s
            {
                unsigned long long ap[4];
                SPLAT2(ap[0], a0.x); SPLAT2(ap[1], a0.y);
                SPLAT2(ap[2], a0.z); SPLAT2(ap[3], a0.w);
                #pragma unroll
                for (int jp = 0; jp < 4; jp++) {
                    FMA2(acc[0][jp], ap[0], bq[jp]);
                    FMA2(acc[1][jp], ap[1], bq[jp]);
                    FMA2(acc[2][jp], ap[2], bq[jp]);
                    FMA2(acc[3][jp], ap[3], bq[jp]);
                }
            }
            // half 2: rows 4..7
            {
                unsigned long long ap[4];
                SPLAT2(ap[0], a1.x); SPLAT2(ap[1], a1.y);
                SPLAT2(ap[2], a1.z); SPLAT2(ap[3], a1.w);
                #pragma unroll
                for (int jp = 0; jp < 4; jp++) {
                    FMA2(acc[4][jp], ap[0], bq[jp]);
                    FMA2(acc[5][jp], ap[1], bq[jp]);
                    FMA2(acc[6][jp], ap[2], bq[jp]);
                    FMA2(acc[7][jp], ap[3], bq[jp]);
                }
            }
        }

        if (has_next) {
            float* dA = sAs[buf ^ 1];
            float* dB = sBs[buf ^ 1];
            dA[(lcol + 0) * TROW + lrow] = pa0.x; dA[(lcol + 1) * TROW + lrow] = pa0.y;
            dA[(lcol + 2) * TROW + lrow] = pa0.z; dA[(lcol + 3) * TROW + lrow] = pa0.w;
            dA[(lcol + 4) * TROW + lrow] = pa1.x; dA[(lcol + 5) * TROW + lrow] = pa1.y;
            dA[(lcol + 6) * TROW + lrow] = pa1.z; dA[(lcol + 7) * TROW + lrow] = pa1.w;
            dB[(lcol + 0) * TROW + lrow] = pb0.x; dB[(lcol + 1) * TROW + lrow] = pb0.y;
            dB[(lcol + 2) * TROW + lrow] = pb0.z; dB[(lcol + 3) * TROW + lrow] = pb0.w;
            dB[(lcol + 4) * TROW + lrow] = pb1.x; dB[(lcol + 5) * TROW + lrow] = pb1.y;
            dB[(lcol + 6) * TROW + lrow] = pb1.z; dB[(lcol + 7) * TROW + lrow] = pb1.w;
        }
        __syncthreads();
    }

    // 8-k tail (k = 240..247 of a 248-panel), buffer nfull&1
    if (has_tail) {
        const float* As = sAs[nfull & 1];
        const float* Bs = sBs[nfull & 1];
        #pragma unroll
        for (int k = 0; k < 8; k++) {
            ulonglong2 bp0 = *reinterpret_cast<const ulonglong2*>(Bs + k * TROW + tx * 8);
            ulonglong2 bp1 = *reinterpret_cast<const ulonglong2*>(Bs + k * TROW + tx * 8 + 4);
            unsigned long long bq[4] = {bp0.x, bp0.y, bp1.x, bp1.y};
            float4 a0 = *reinterpret_cast<const float4*>(As + k * TROW + ty * 8);
            float4 a1 = *reinterpret_cast<const float4*>(As + k * TROW + ty * 8 + 4);
            {
                unsigned long long ap[4];
                SPLAT2(ap[0], a0.x); SPLAT2(ap[1], a0.y);
                SPLAT2(ap[2], a0.z); SPLAT2(ap[3], a0.w);
                #pragma unroll
                for (int jp = 0; jp < 4; jp++) {
                    FMA2(acc[0][jp], ap[0], bq[jp]);
                    FMA2(acc[1][jp], ap[1], bq[jp]);
                    FMA2(acc[2][jp], ap[2], bq[jp]);
                    FMA2(acc[3][jp], ap[3], bq[jp]);
                }
            }
            {
                unsigned long long ap[4];
                SPLAT2(ap[0], a1.x); SPLAT2(ap[1], a1.y);
                SPLAT2(ap[2], a1.z); SPLAT2(ap[3], a1.w);
                #pragma unroll
                for (int jp = 0; jp < 4; jp++) {
                    FMA2(acc[4][jp], ap[0], bq[jp]);
                    FMA2(acc[5][jp], ap[1], bq[jp]);
                    FMA2(acc[6][jp], ap[2], bq[jp]);
                    FMA2(acc[7][jp], ap[3], bq[jp]);
                }
            }
        }
    }

    // write panel partials (u64 store = {lo=col even, hi=col odd})
    float* part = g_part[p];
    #pragma unroll
    for (int i = 0; i < 8; i++) {
        int row = tile_m + ty * 8 + i;
        float* base = part + (size_t)row * E + tile_n + tx * 8;
        #pragma unroll
        for (int jp = 0; jp < 4; jp++)
            *reinterpret_cast<unsigned long long*>(base + 2 * jp) = acc[i][jp];
    }
}

// ---------------------------------------------------------------------------
// XLA:CPU fused-loop sigmoid (FROZEN): 1/(1+exp(-x)), exp via VF32Exp with
// fused n = floor(fma(x, log2e, 0.5)).
// ---------------------------------------------------------------------------
__device__ __forceinline__ float vf32_exp(float x) {
    x = fminf(fmaxf(x, -87.8f), 88.8f);
    float fx = floorf(__fmaf_rn(x, 1.44269504088896341f, 0.5f));
    float tmp = __fmul_rn(fx, 0.693359375f);
    float z   = __fmul_rn(fx, -2.12194440e-4f);
    float r = __fsub_rn(__fsub_rn(x, tmp), z);
    float r2 = __fmul_rn(r, r);
    float y = 1.9875691500e-4f;
    y = __fmaf_rn(y, r, 1.3981999507e-3f);
    y = __fmaf_rn(y, r, 8.3334519073e-3f);
    y = __fmaf_rn(y, r, 4.1665795894e-2f);
    y = __fmaf_rn(y, r, 1.6666665459e-1f);
    y = __fmaf_rn(y, r, 5.0000001201e-1f);
    y = __fmaf_rn(y, r2, r);
    y = __fadd_rn(y, 1.0f);
    int n = (int)fx;
    return __fmul_rn(y, __int_as_float((n + 127) << 23));
}

__device__ __forceinline__ float xla_cpu_sigmoid(float x) {
    float e = vf32_exp(-x);
    return __fdiv_rn(1.0f, __fadd_rn(1.0f, e));
}

// ---------------------------------------------------------------------------
// Kernel 2: fold panels (ascending p, rn adds — Eigen order) + routing.
// One block (256 threads) per token. (FROZEN semantics)
// ---------------------------------------------------------------------------
__global__ __launch_bounds__(256) void router_topk(
    const float* __restrict__ bias,
    float* __restrict__ out_idx,
    float* __restrict__ out_w)
{
    __shared__ float s_score[NEXP];
    __shared__ float s_masked[NEXP];
    __shared__ float s_gscore[NGROUP];
    __shared__ int   s_gmask[NGROUP];
    __shared__ int   s_sel[TOPKN];

    const int t = blockIdx.x;
    const int e = threadIdx.x;
    const int warp = e >> 5, lane = e & 31;

    // fold partials: MLP-29 gather, then exact ascending rn-fold
    float v[NPANEL];
    #pragma unroll
    for (int p = 0; p < NPANEL; p++)
        v[p] = g_part[p][(size_t)t * NEXP + e];
    float logit = 0.0f;
    #pragma unroll
    for (int p = 0; p < NPANEL; p++)
        logit = __fadd_rn(logit, v[p]);

    float score = xla_cpu_sigmoid(logit);
    float corr = __fadd_rn(score, bias[e]);
    s_score[e] = score;

    float m1 = corr;
    #pragma unroll
    for (int o = 16; o > 0; o >>= 1)
        m1 = fmaxf(m1, __shfl_xor_sync(0xffffffffu, m1, o));
    unsigned ball = __ballot_sync(0xffffffffu, corr == m1);
    int firstlane = __ffs(ball) - 1;
    float v2 = (lane == firstlane) ? -INFINITY : corr;
    float m2 = v2;
    #pragma unroll
    for (int o = 16; o > 0; o >>= 1)
        m2 = fmaxf(m2, __shfl_xor_sync(0xffffffffu, m2, o));
    if (lane == 0) s_gscore[warp] = __fadd_rn(m1, m2);
    __syncthreads();

    if (e == 0) {
        bool used[NGROUP];
        #pragma unroll
        for (int g = 0; g < NGROUP; g++) used[g] = false;
        for (int it = 0; it < TOPKG; it++) {
            float best = -INFINITY; int bi = 0;
            for (int g = 0; g < NGROUP; g++)
                if (!used[g] && s_gscore[g] > best) { best = s_gscore[g]; bi = g; }
            used[bi] = true;
        }
        #pragma unroll
        for (int g = 0; g < NGROUP; g++) s_gmask[g] = used[g] ? 1 : 0;
    }
    __syncthreads();

    s_masked[e] = s_gmask[warp] ? corr : 0.0f;
    __syncthreads();

    if (warp == 0) {
        float lv[8];
        #pragma unroll
        for (int i = 0; i < 8; i++) lv[i] = s_masked[lane + i * 32];

        for (int it = 0; it < TOPKN; it++) {
            float best = -INFINITY; int bslot = 0;
            #pragma unroll
            for (int i = 0; i < 8; i++)
                if (lv[i] > best) { best = lv[i]; bslot = i; }
            int bidx = bslot * 32 + lane;
            #pragma unroll
            for (int o = 16; o > 0; o >>= 1) {
                float ov = __shfl_xor_sync(0xffffffffu, best, o);
                int   oi = __shfl_xor_sync(0xffffffffu, bidx, o);
                if (ov > best || (ov == best && oi < bidx)) { best = ov; bidx = oi; }
            }
            if (lane == 0) s_sel[it] = bidx;
            if (lane == (bidx & 31)) lv[bidx >> 5] = -INFINITY;
        }
        __syncwarp();

        float w = 0.0f;
        int myidx = 0;
        if (lane < TOPKN) {
            myidx = s_sel[lane];
            w = s_score[myidx];
        }
        float ws = w;
        #pragma unroll
        for (int o = 16; o > 0; o >>= 1)
            ws += __shfl_xor_sync(0xffffffffu, ws, o);
        if (lane < TOPKN) {
            float wn = __fmul_rn(__fdiv_rn(w, __fadd_rn(ws, 1e-20f)), 2.5f);
            out_idx[(size_t)t * TOPKN + lane] = (float)myidx;
            out_w[(size_t)t * TOPKN + lane] = wn;
        }
    }
}

// ---------------------------------------------------------------------------
extern "C" void kernel_launch(void* const* d_in, const int* in_sizes, int n_in,
                              void* d_out, int out_size) {
    const float* hidden = (const float*)d_in[0];
    const float* weight = (const float*)d_in[1];
    const float* bias   = (const float*)d_in[2];

    int E = in_sizes[2];
    int H = in_sizes[1] / E;
    int T = in_sizes[0] / H;

    dim3 gemm_grid(E / BN, T / BM, NPANEL);
    router_gemm_panel<<<gemm_grid, 256>>>(hidden, weight, T, H, E);

    float* out = (float*)d_out;
    router_topk<<<T, 256>>>(bias, out, out + (size_t)T * TOPKN);
}